// round 1
// baseline (speedup 1.0000x reference)
#include <cuda_runtime.h>

#define NPTS 2097152
#define NSTK 500

using ull = unsigned long long;

// ---- packed f32x2 helpers (sm_103a) ----
__device__ __forceinline__ ull pk2(float lo, float hi) {
    ull r; asm("mov.b64 %0, {%1, %2};" : "=l"(r) : "f"(lo), "f"(hi)); return r;
}
__device__ __forceinline__ void up2(ull v, float& a, float& b) {
    asm("mov.b64 {%0, %1}, %2;" : "=f"(a), "=f"(b) : "l"(v));
}
__device__ __forceinline__ ull add2(ull a, ull b) {
    ull r; asm("add.rn.f32x2 %0, %1, %2;" : "=l"(r) : "l"(a), "l"(b)); return r;
}
__device__ __forceinline__ ull mul2(ull a, ull b) {
    ull r; asm("mul.rn.f32x2 %0, %1, %2;" : "=l"(r) : "l"(a), "l"(b)); return r;
}
__device__ __forceinline__ ull fma2(ull a, ull b, ull c) {
    ull r; asm("fma.rn.f32x2 %0, %1, %2, %3;" : "=l"(r) : "l"(a), "l"(b), "l"(c)); return r;
}
__device__ __forceinline__ float sqapx(float x) {
    float r; asm("sqrt.approx.f32 %0, %1;" : "=f"(r) : "f"(x)); return r;
}

#define ONE2   0x3f8000003f800000ull
#define NEG12  0xbf800000bf800000ull

// Each thread processes 4 points as 2 packed f32x2 pairs.
// Shared holds per-stroke params pre-duplicated into packed pairs:
//   ss[4s+0] = { (-cx,-cx), (-cy,-cy) }
//   ss[4s+1] = { (-cz,-cz), ( A , A ) }   A = 0.5 + 5*r   (t = sat(A - 5*dist))
//   ss[4s+2] = { ( d , d ), ( cr, cr) }   d = max(alpha,0)*50
//   ss[4s+3] = { ( cg, cg), ( cb, cb) }
__global__ void __launch_bounds__(256, 2)
stroke_kernel(const float* __restrict__ coords,
              const float* __restrict__ shape,
              const float* __restrict__ color,
              const float* __restrict__ alpha,
              float* __restrict__ out)
{
    __shared__ ulonglong2 ss[NSTK * 4];

    for (int s = threadIdx.x; s < NSTK; s += blockDim.x) {
        float cx = shape[4 * s + 0];
        float cy = shape[4 * s + 1];
        float cz = shape[4 * s + 2];
        float r  = shape[4 * s + 3];
        float A  = fmaf(5.0f, r, 0.5f);
        float d  = fmaxf(alpha[s], 0.0f) * 50.0f;
        float cr = color[3 * s + 0];
        float cg = color[3 * s + 1];
        float cb = color[3 * s + 2];
        ss[4 * s + 0] = make_ulonglong2(pk2(-cx, -cx), pk2(-cy, -cy));
        ss[4 * s + 1] = make_ulonglong2(pk2(-cz, -cz), pk2(A, A));
        ss[4 * s + 2] = make_ulonglong2(pk2(d, d),     pk2(cr, cr));
        ss[4 * s + 3] = make_ulonglong2(pk2(cg, cg),   pk2(cb, cb));
    }
    __syncthreads();

    const int t    = blockIdx.x * blockDim.x + threadIdx.x;
    const int base = t * 4;

    // ---- load + contract 4 points, emit warped-coord output ----
    float wx[4], wy[4], wz[4];
#pragma unroll
    for (int i = 0; i < 4; i++) {
        const int p = base + i;
        float x = coords[3 * p + 0];
        float y = coords[3 * p + 1];
        float z = coords[3 * p + 2];
        float n2 = fmaf(x, x, fmaf(y, y, z * z));
        float n  = fmaxf(sqrtf(n2), 1e-9f);
        float sc = 0.5f;                       // contract(x)/2 inside unit ball
        if (n > 1.0f) sc = (2.0f - 1.0f / n) / n * 0.5f;
        wx[i] = x * sc; wy[i] = y * sc; wz[i] = z * sc;
        out[4 * NPTS + 3 * p + 0] = wx[i];
        out[4 * NPTS + 3 * p + 1] = wy[i];
        out[4 * NPTS + 3 * p + 2] = wz[i];
    }

    ull cx2[2] = { pk2(wx[0], wx[1]), pk2(wx[2], wx[3]) };
    ull cy2[2] = { pk2(wy[0], wy[1]), pk2(wy[2], wy[3]) };
    ull cz2[2] = { pk2(wz[0], wz[1]), pk2(wz[2], wz[3]) };

    ull hd[2] = { 0ull, 0ull };
    ull hr[2] = { 0ull, 0ull };
    ull hg[2] = { 0ull, 0ull };
    ull hb[2] = { 0ull, 0ull };
    ull hw[2] = { ONE2, ONE2 };

#pragma unroll 2
    for (int s = 0; s < NSTK; s++) {
        ulonglong2 v0 = ss[4 * s + 0];
        ulonglong2 v1 = ss[4 * s + 1];
        ulonglong2 v2 = ss[4 * s + 2];
        ulonglong2 v3 = ss[4 * s + 3];
        float A, Adup; up2(v1.y, A, Adup);
#pragma unroll
        for (int p = 0; p < 2; p++) {
            ull dx = add2(cx2[p], v0.x);
            ull dy = add2(cy2[p], v0.y);
            ull dz = add2(cz2[p], v1.x);
            ull d2 = mul2(dx, dx);
            d2 = fma2(dy, dy, d2);
            d2 = fma2(dz, dz, d2);
            float qa, qb; up2(d2, qa, qb);
            float ta = __saturatef(fmaf(sqapx(qa), -5.0f, A));
            float tb = __saturatef(fmaf(sqapx(qb), -5.0f, A));
            ull t2  = pk2(ta, tb);
            ull omt = fma2(t2, NEG12, ONE2);           // 1 - t
            hd[p] = fma2(t2, v2.x, mul2(omt, hd[p]));
            hr[p] = fma2(t2, v2.y, mul2(omt, hr[p]));
            hg[p] = fma2(t2, v3.x, mul2(omt, hg[p]));
            hb[p] = fma2(t2, v3.y, mul2(omt, hb[p]));
            hw[p] = mul2(omt, hw[p]);
        }
    }

    // ---- epilogue: density + rgb ----
#pragma unroll
    for (int p = 0; p < 2; p++) {
        float d0, d1, w0, w1, r0, r1, g0, g1, b0, b1;
        up2(hd[p], d0, d1);
        up2(hw[p], w0, w1);
        up2(hr[p], r0, r1);
        up2(hg[p], g0, g1);
        up2(hb[p], b0, b1);
        int i0 = base + 2 * p;
        int i1 = i0 + 1;
        out[i0] = d0;
        out[i1] = d1;
        float inv0 = 1.0f / (1.0f + 1e-6f - w0);
        float inv1 = 1.0f / (1.0f + 1e-6f - w1);
        out[NPTS + 3 * i0 + 0] = __saturatef(r0 * inv0);
        out[NPTS + 3 * i0 + 1] = __saturatef(g0 * inv0);
        out[NPTS + 3 * i0 + 2] = __saturatef(b0 * inv0);
        out[NPTS + 3 * i1 + 0] = __saturatef(r1 * inv1);
        out[NPTS + 3 * i1 + 1] = __saturatef(g1 * inv1);
        out[NPTS + 3 * i1 + 2] = __saturatef(b1 * inv1);
    }
}

extern "C" void kernel_launch(void* const* d_in, const int* in_sizes, int n_in,
                              void* d_out, int out_size)
{
    const float* coords = (const float*)d_in[0];
    const float* shape  = (const float*)d_in[1];
    const float* color  = (const float*)d_in[2];
    const float* alpha  = (const float*)d_in[3];
    float* out = (float*)d_out;

    const int threads = 256;
    const int blocks  = NPTS / (4 * threads);   // 2048
    stroke_kernel<<<blocks, threads>>>(coords, shape, color, alpha, out);
}

// round 2
// speedup vs baseline: 2.1805x; 2.1805x over previous
#include <cuda_runtime.h>

#define NPTS 2097152
#define NSTK 500
#define G    16
#define NC   (G*G*G)          // 4096 cells
#define TASK 256              // points per task
#define MAXT (NC + NPTS/TASK) // 12288

using ull = unsigned long long;

// ---- packed f32x2 helpers (sm_103a) ----
__device__ __forceinline__ ull pk2(float lo, float hi) {
    ull r; asm("mov.b64 %0, {%1, %2};" : "=l"(r) : "f"(lo), "f"(hi)); return r;
}
__device__ __forceinline__ void up2(ull v, float& a, float& b) {
    asm("mov.b64 {%0, %1}, %2;" : "=f"(a), "=f"(b) : "l"(v));
}
__device__ __forceinline__ ull add2(ull a, ull b) {
    ull r; asm("add.rn.f32x2 %0, %1, %2;" : "=l"(r) : "l"(a), "l"(b)); return r;
}
__device__ __forceinline__ ull mul2(ull a, ull b) {
    ull r; asm("mul.rn.f32x2 %0, %1, %2;" : "=l"(r) : "l"(a), "l"(b)); return r;
}
__device__ __forceinline__ ull fma2(ull a, ull b, ull c) {
    ull r; asm("fma.rn.f32x2 %0, %1, %2, %3;" : "=l"(r) : "l"(a), "l"(b), "l"(c)); return r;
}
__device__ __forceinline__ float sqapx(float x) {
    float r; asm("sqrt.approx.f32 %0, %1;" : "=f"(r) : "f"(x)); return r;
}

#define ONE2   0x3f8000003f800000ull
#define NEG12  0xbf800000bf800000ull

// ---- scratch (device globals; no allocations) ----
__device__ float4      g_pc[NPTS];          // wx,wy,wz, cell-as-bits
__device__ float4      g_sorted[NPTS];      // wx,wy,wz, origidx-as-bits
__device__ int         g_hist[NC];
__device__ int         g_off[NC];
__device__ int         g_cursor[NC];
__device__ int         g_cellCnt[NC];
__device__ int         g_cellList[NC * NSTK];
__device__ ulonglong2  g_spk[NSTK * 4];     // packed stroke params
__device__ float4      g_sc[NSTK];          // cx,cy,cz, R=r+0.1+eps
__device__ int4        g_tasks[MAXT];
__device__ int         g_taskCount;

__device__ __forceinline__ int cellOf(float x, float y, float z) {
    int ix = min(max(__float2int_rd((x + 1.0f) * 8.0f), 0), G - 1);
    int iy = min(max(__float2int_rd((y + 1.0f) * 8.0f), 0), G - 1);
    int iz = min(max(__float2int_rd((z + 1.0f) * 8.0f), 0), G - 1);
    return ix | (iy << 4) | (iz << 8);
}

// ---------- K0: zero counters ----------
__global__ void k_zero() {
    int i = blockIdx.x * blockDim.x + threadIdx.x;
    if (i < NC) g_hist[i] = 0;
    if (i == 0) g_taskCount = 0;
}

// ---------- K1: pack strokes ----------
__global__ void k_prep(const float* __restrict__ shape,
                       const float* __restrict__ color,
                       const float* __restrict__ alpha) {
    int s = blockIdx.x * blockDim.x + threadIdx.x;
    if (s >= NSTK) return;
    float cx = shape[4 * s + 0], cy = shape[4 * s + 1];
    float cz = shape[4 * s + 2], r = shape[4 * s + 3];
    float A  = fmaf(5.0f, r, 0.5f);
    float d  = fmaxf(alpha[s], 0.0f) * 50.0f;
    float cr = color[3 * s + 0], cg = color[3 * s + 1], cb = color[3 * s + 2];
    g_spk[4 * s + 0] = make_ulonglong2(pk2(-cx, -cx), pk2(-cy, -cy));
    g_spk[4 * s + 1] = make_ulonglong2(pk2(-cz, -cz), pk2(A, A));
    g_spk[4 * s + 2] = make_ulonglong2(pk2(d, d),     pk2(cr, cr));
    g_spk[4 * s + 3] = make_ulonglong2(pk2(cg, cg),   pk2(cb, cb));
    g_sc[s] = make_float4(cx, cy, cz, r + 0.1f + 1e-4f);
}

// ---------- K2: warp coords, emit coord output, histogram ----------
__global__ void __launch_bounds__(256)
k_warp(const float* __restrict__ coords, float* __restrict__ out) {
    const int t = blockIdx.x * blockDim.x + threadIdx.x;
#pragma unroll
    for (int i = 0; i < 4; i++) {
        const int p = t * 4 + i;
        float x = coords[3 * p + 0];
        float y = coords[3 * p + 1];
        float z = coords[3 * p + 2];
        float n2 = fmaf(x, x, fmaf(y, y, z * z));
        float n  = fmaxf(sqrtf(n2), 1e-9f);
        float sc = 0.5f;
        if (n > 1.0f) sc = (2.0f - 1.0f / n) / n * 0.5f;
        float wx = x * sc, wy = y * sc, wz = z * sc;
        out[4 * NPTS + 3 * p + 0] = wx;
        out[4 * NPTS + 3 * p + 1] = wy;
        out[4 * NPTS + 3 * p + 2] = wz;
        int c = cellOf(wx, wy, wz);
        atomicAdd(&g_hist[c], 1);
        g_pc[p] = make_float4(wx, wy, wz, __int_as_float(c));
    }
}

// ---------- K3: exclusive scan over 4096 cells (1 block, 1024 thr) ----------
__global__ void k_scan() {
    __shared__ int sh[1024];
    int tid = threadIdx.x;
    int b4 = tid * 4;
    int v0 = g_hist[b4 + 0], v1 = g_hist[b4 + 1];
    int v2 = g_hist[b4 + 2], v3 = g_hist[b4 + 3];
    int s = v0 + v1 + v2 + v3;
    sh[tid] = s;
    __syncthreads();
    for (int off = 1; off < 1024; off <<= 1) {
        int t = (tid >= off) ? sh[tid - off] : 0;
        __syncthreads();
        sh[tid] += t;
        __syncthreads();
    }
    int o = sh[tid] - s;
    g_off[b4 + 0] = o; g_cursor[b4 + 0] = o; o += v0;
    g_off[b4 + 1] = o; g_cursor[b4 + 1] = o; o += v1;
    g_off[b4 + 2] = o; g_cursor[b4 + 2] = o; o += v2;
    g_off[b4 + 3] = o; g_cursor[b4 + 3] = o;
}

// ---------- K4: scatter points into cell-sorted order ----------
__global__ void __launch_bounds__(256)
k_scatter() {
    int p = blockIdx.x * blockDim.x + threadIdx.x;
    float4 v = g_pc[p];
    int c = __float_as_int(v.w);
    int pos = atomicAdd(&g_cursor[c], 1);
    g_sorted[pos] = make_float4(v.x, v.y, v.z, __int_as_float(p));
}

// ---------- K5: per-cell stroke culling + task building ----------
__global__ void k_cull() {
    int c = blockIdx.x * blockDim.x + threadIdx.x;
    if (c >= NC) return;
    int ix = c & 15, iy = (c >> 4) & 15, iz = c >> 8;
    float lox = -1.0f + ix * 0.125f, hix = lox + 0.125f;
    float loy = -1.0f + iy * 0.125f, hiy = loy + 0.125f;
    float loz = -1.0f + iz * 0.125f, hiz = loz + 0.125f;
    int cnt = 0;
    for (int s = 0; s < NSTK; s++) {
        float4 sc = g_sc[s];
        float dx = fmaxf(fmaxf(lox - sc.x, sc.x - hix), 0.0f);
        float dy = fmaxf(fmaxf(loy - sc.y, sc.y - hiy), 0.0f);
        float dz = fmaxf(fmaxf(loz - sc.z, sc.z - hiz), 0.0f);
        float d2 = fmaf(dx, dx, fmaf(dy, dy, dz * dz));
        if (d2 < sc.w * sc.w) g_cellList[c * NSTK + cnt++] = s;
    }
    g_cellCnt[c] = cnt;
    int np = g_hist[c];
    if (np > 0) {
        int nt = (np + TASK - 1) / TASK;
        int base = atomicAdd(&g_taskCount, nt);
        int st = g_off[c];
        for (int k = 0; k < nt; k++) {
            int a = st + k * TASK;
            int e = min(st + np, a + TASK);
            g_tasks[base + k] = make_int4(c, a, e, 0);
        }
    }
}

// ---------- K6: main blend (one task = 256 same-cell points) ----------
__global__ void __launch_bounds__(128)
k_main(float* __restrict__ out) {
    int b = blockIdx.x;
    if (b >= g_taskCount) return;
    int4 tk = g_tasks[b];
    const int cell = tk.x, start = tk.y, end = tk.z;
    const int m = g_cellCnt[cell];

    __shared__ ulonglong2 sm[NSTK * 4];   // 32KB max
    const int* __restrict__ list = &g_cellList[cell * NSTK];
    for (int j = threadIdx.x; j < m; j += 128) {
        int s = list[j];
        sm[4 * j + 0] = g_spk[4 * s + 0];
        sm[4 * j + 1] = g_spk[4 * s + 1];
        sm[4 * j + 2] = g_spk[4 * s + 2];
        sm[4 * j + 3] = g_spk[4 * s + 3];
    }
    __syncthreads();

    const int pos0 = start + threadIdx.x * 2;
    const int pos1 = pos0 + 1;
    const bool ok0 = pos0 < end, ok1 = pos1 < end;
    float4 a = ok0 ? g_sorted[pos0] : make_float4(0, 0, 0, 0);
    float4 bpt = ok1 ? g_sorted[pos1] : make_float4(0, 0, 0, 0);

    ull cxx = pk2(a.x, bpt.x);
    ull cyy = pk2(a.y, bpt.y);
    ull czz = pk2(a.z, bpt.z);

    ull hd = 0ull, hr = 0ull, hg = 0ull, hb = 0ull, hw = ONE2;

#pragma unroll 2
    for (int j = 0; j < m; j++) {
        ulonglong2 v0 = sm[4 * j + 0];
        ulonglong2 v1 = sm[4 * j + 1];
        ulonglong2 v2 = sm[4 * j + 2];
        ulonglong2 v3 = sm[4 * j + 3];
        float A, Ad; up2(v1.y, A, Ad);
        ull dx = add2(cxx, v0.x);
        ull dy = add2(cyy, v0.y);
        ull dz = add2(czz, v1.x);
        ull d2 = mul2(dx, dx);
        d2 = fma2(dy, dy, d2);
        d2 = fma2(dz, dz, d2);
        float qa, qb; up2(d2, qa, qb);
        float ta = __saturatef(fmaf(sqapx(qa), -5.0f, A));
        float tb = __saturatef(fmaf(sqapx(qb), -5.0f, A));
        ull t2  = pk2(ta, tb);
        ull omt = fma2(t2, NEG12, ONE2);
        hd = fma2(t2, v2.x, mul2(omt, hd));
        hr = fma2(t2, v2.y, mul2(omt, hr));
        hg = fma2(t2, v3.x, mul2(omt, hg));
        hb = fma2(t2, v3.y, mul2(omt, hb));
        hw = mul2(omt, hw);
    }

    float d0, d1, w0, w1, r0, r1, g0, g1, b0, b1;
    up2(hd, d0, d1);
    up2(hw, w0, w1);
    up2(hr, r0, r1);
    up2(hg, g0, g1);
    up2(hb, b0, b1);

    if (ok0) {
        int i0 = __float_as_int(a.w);
        float inv = 1.0f / (1.0f + 1e-6f - w0);
        out[i0] = d0;
        out[NPTS + 3 * i0 + 0] = __saturatef(r0 * inv);
        out[NPTS + 3 * i0 + 1] = __saturatef(g0 * inv);
        out[NPTS + 3 * i0 + 2] = __saturatef(b0 * inv);
    }
    if (ok1) {
        int i1 = __float_as_int(bpt.w);
        float inv = 1.0f / (1.0f + 1e-6f - w1);
        out[i1] = d1;
        out[NPTS + 3 * i1 + 0] = __saturatef(r1 * inv);
        out[NPTS + 3 * i1 + 1] = __saturatef(g1 * inv);
        out[NPTS + 3 * i1 + 2] = __saturatef(b1 * inv);
    }
}

extern "C" void kernel_launch(void* const* d_in, const int* in_sizes, int n_in,
                              void* d_out, int out_size)
{
    const float* coords = (const float*)d_in[0];
    const float* shape  = (const float*)d_in[1];
    const float* color  = (const float*)d_in[2];
    const float* alpha  = (const float*)d_in[3];
    float* out = (float*)d_out;

    k_zero<<<(NC + 255) / 256, 256>>>();
    k_prep<<<2, 256>>>(shape, color, alpha);
    k_warp<<<NPTS / (4 * 256), 256>>>(coords, out);
    k_scan<<<1, 1024>>>();
    k_scatter<<<NPTS / 256, 256>>>();
    k_cull<<<NC / 256, 256>>>();
    k_main<<<MAXT, 128>>>(out);
}

// round 3
// speedup vs baseline: 2.2335x; 1.0243x over previous
#include <cuda_runtime.h>

#define NPTS 2097152
#define NSTK 500
#define G    32
#define NC   (G*G*G)            // 32768 cells
#define TASK 512                // points per task (128 thr * 4 pts)
#define MAXT (NC + NPTS/TASK)   // 36864

using ull = unsigned long long;

// ---- packed f32x2 helpers (sm_103a) ----
__device__ __forceinline__ ull pk2(float lo, float hi) {
    ull r; asm("mov.b64 %0, {%1, %2};" : "=l"(r) : "f"(lo), "f"(hi)); return r;
}
__device__ __forceinline__ void up2(ull v, float& a, float& b) {
    asm("mov.b64 {%0, %1}, %2;" : "=f"(a), "=f"(b) : "l"(v));
}
__device__ __forceinline__ ull add2(ull a, ull b) {
    ull r; asm("add.rn.f32x2 %0, %1, %2;" : "=l"(r) : "l"(a), "l"(b)); return r;
}
__device__ __forceinline__ ull mul2(ull a, ull b) {
    ull r; asm("mul.rn.f32x2 %0, %1, %2;" : "=l"(r) : "l"(a), "l"(b)); return r;
}
__device__ __forceinline__ ull fma2(ull a, ull b, ull c) {
    ull r; asm("fma.rn.f32x2 %0, %1, %2, %3;" : "=l"(r) : "l"(a), "l"(b), "l"(c)); return r;
}
__device__ __forceinline__ float sqapx(float x) {
    float r; asm("sqrt.approx.f32 %0, %1;" : "=f"(r) : "f"(x)); return r;
}

#define ONE2   0x3f8000003f800000ull
#define NEG12  0xbf800000bf800000ull

// ---- scratch (device globals) ----
__device__ float4      g_sorted[NPTS];       // wx,wy,wz, origidx-as-bits
__device__ int         g_hist[NC];
__device__ int         g_off[NC];
__device__ int         g_cursor[NC];
__device__ int         g_cellCnt[NC];
__device__ int         g_cellList[NC * 192]; // transposed: [j*NC + c], cap 192
__device__ ulonglong2  g_spk[NSTK * 4];      // packed stroke params
__device__ float4      g_sc[NSTK];           // cx,cy,cz, R=r+0.1+eps
__device__ int4        g_tasks[MAXT];
__device__ int         g_taskCount;

#define MAXL 192

__device__ __forceinline__ int cellOf(float x, float y, float z) {
    int ix = min(max(__float2int_rd((x + 1.0f) * 16.0f), 0), G - 1);
    int iy = min(max(__float2int_rd((y + 1.0f) * 16.0f), 0), G - 1);
    int iz = min(max(__float2int_rd((z + 1.0f) * 16.0f), 0), G - 1);
    return ix | (iy << 5) | (iz << 10);
}

__device__ __forceinline__ void warp_pt(float x, float y, float z,
                                        float& wx, float& wy, float& wz) {
    float n2 = fmaf(x, x, fmaf(y, y, z * z));
    float n  = fmaxf(sqrtf(n2), 1e-9f);
    float sc = 0.5f;
    if (n > 1.0f) sc = (2.0f - 1.0f / n) / n * 0.5f;
    wx = x * sc; wy = y * sc; wz = z * sc;
}

// ---------- K1: zero counters + pack strokes ----------
__global__ void k_prep(const float* __restrict__ shape,
                       const float* __restrict__ color,
                       const float* __restrict__ alpha) {
    int i = blockIdx.x * blockDim.x + threadIdx.x;
    if (i < NC) g_hist[i] = 0;
    if (i == 0) g_taskCount = 0;
    if (i < NSTK) {
        int s = i;
        float cx = shape[4 * s + 0], cy = shape[4 * s + 1];
        float cz = shape[4 * s + 2], r = shape[4 * s + 3];
        float A  = fmaf(5.0f, r, 0.5f);
        float B2 = (A * 0.2f) * (A * 0.2f);          // skip iff d2 >= B2
        float d  = fmaxf(alpha[s], 0.0f) * 50.0f;
        float cr = color[3 * s + 0], cg = color[3 * s + 1], cb = color[3 * s + 2];
        g_spk[4 * s + 0] = make_ulonglong2(pk2(-cx, -cx), pk2(-cy, -cy));
        g_spk[4 * s + 1] = make_ulonglong2(pk2(-cz, -cz), pk2(A, B2));
        g_spk[4 * s + 2] = make_ulonglong2(pk2(d, d),     pk2(cr, cr));
        g_spk[4 * s + 3] = make_ulonglong2(pk2(cg, cg),   pk2(cb, cb));
        g_sc[s] = make_float4(cx, cy, cz, r + 0.1f + 1e-4f);
    }
}

// ---------- K2: warp coords, emit coord output, histogram ----------
__global__ void __launch_bounds__(256)
k_hist(const float* __restrict__ coords, float* __restrict__ out) {
    const int t = blockIdx.x * blockDim.x + threadIdx.x;
#pragma unroll
    for (int i = 0; i < 4; i++) {
        const int p = t * 4 + i;
        float wx, wy, wz;
        warp_pt(coords[3 * p + 0], coords[3 * p + 1], coords[3 * p + 2], wx, wy, wz);
        out[4 * NPTS + 3 * p + 0] = wx;
        out[4 * NPTS + 3 * p + 1] = wy;
        out[4 * NPTS + 3 * p + 2] = wz;
        atomicAdd(&g_hist[cellOf(wx, wy, wz)], 1);
    }
}

// ---------- K3: exclusive scan over 32768 cells (1 block, 1024 thr) ----------
__global__ void k_scan() {
    __shared__ int warpsum[32];
    int tid = threadIdx.x;
    int lane = tid & 31, wid = tid >> 5;
    int base = tid * 32;
    int v[32];
    int s = 0;
#pragma unroll
    for (int k = 0; k < 32; k++) { v[k] = g_hist[base + k]; s += v[k]; }
    // inclusive warp scan of s
    int ps = s;
#pragma unroll
    for (int off = 1; off < 32; off <<= 1) {
        int t = __shfl_up_sync(0xffffffff, ps, off);
        if (lane >= off) ps += t;
    }
    if (lane == 31) warpsum[wid] = ps;
    __syncthreads();
    if (wid == 0) {
        int w = warpsum[lane];
        int pw = w;
#pragma unroll
        for (int off = 1; off < 32; off <<= 1) {
            int t = __shfl_up_sync(0xffffffff, pw, off);
            if (lane >= off) pw += t;
        }
        warpsum[lane] = pw - w;   // exclusive
    }
    __syncthreads();
    int o = warpsum[wid] + ps - s;   // exclusive prefix for this thread's chunk
#pragma unroll
    for (int k = 0; k < 32; k++) {
        g_off[base + k] = o;
        g_cursor[base + k] = o;
        o += v[k];
    }
}

// ---------- K4: recompute warp, scatter points into cell-sorted order ----------
__global__ void __launch_bounds__(256)
k_scatter(const float* __restrict__ coords) {
    const int t = blockIdx.x * blockDim.x + threadIdx.x;
#pragma unroll
    for (int i = 0; i < 4; i++) {
        const int p = t * 4 + i;
        float wx, wy, wz;
        warp_pt(coords[3 * p + 0], coords[3 * p + 1], coords[3 * p + 2], wx, wy, wz);
        int c = cellOf(wx, wy, wz);
        int pos = atomicAdd(&g_cursor[c], 1);
        g_sorted[pos] = make_float4(wx, wy, wz, __int_as_float(p));
    }
}

// ---------- K5: per-cell stroke culling + task building ----------
__global__ void __launch_bounds__(256)
k_cull() {
    int c = blockIdx.x * blockDim.x + threadIdx.x;
    if (c >= NC) return;
    int ix = c & 31, iy = (c >> 5) & 31, iz = c >> 10;
    const float cs = 0.0625f;
    float lox = -1.0f + ix * cs, hix = lox + cs;
    float loy = -1.0f + iy * cs, hiy = loy + cs;
    float loz = -1.0f + iz * cs, hiz = loz + cs;
    int cnt = 0;
    for (int s = 0; s < NSTK; s++) {
        float4 sc = g_sc[s];
        float dx = fmaxf(fmaxf(lox - sc.x, sc.x - hix), 0.0f);
        float dy = fmaxf(fmaxf(loy - sc.y, sc.y - hiy), 0.0f);
        float dz = fmaxf(fmaxf(loz - sc.z, sc.z - hiz), 0.0f);
        float d2 = fmaf(dx, dx, fmaf(dy, dy, dz * dz));
        if (d2 < sc.w * sc.w && cnt < MAXL) g_cellList[cnt++ * NC + c] = s;
    }
    g_cellCnt[c] = cnt;
    int np = g_hist[c];
    if (np > 0) {
        int nt = (np + TASK - 1) / TASK;
        int b = atomicAdd(&g_taskCount, nt);
        int st = g_off[c];
        for (int k = 0; k < nt; k++) {
            int a = st + k * TASK;
            int e = min(st + np, a + TASK);
            g_tasks[b + k] = make_int4(c, a, e, 0);
        }
    }
}

// ---------- K6: main blend (one task = 512 same-cell points, 4/thread) ----------
__global__ void __launch_bounds__(128)
k_main(float* __restrict__ out) {
    int b = blockIdx.x;
    if (b >= g_taskCount) return;
    int4 tk = g_tasks[b];
    const int cell = tk.x, start = tk.y, end = tk.z;
    const int m = g_cellCnt[cell];

    __shared__ ulonglong2 sm[MAXL * 4];   // 12KB
    for (int j = threadIdx.x; j < m; j += 128) {
        int s = g_cellList[j * NC + cell];
        sm[4 * j + 0] = g_spk[4 * s + 0];
        sm[4 * j + 1] = g_spk[4 * s + 1];
        sm[4 * j + 2] = g_spk[4 * s + 2];
        sm[4 * j + 3] = g_spk[4 * s + 3];
    }
    __syncthreads();

    const int p0 = start + threadIdx.x * 4;
    bool ok[4];
    float4 pt[4];
#pragma unroll
    for (int i = 0; i < 4; i++) {
        ok[i] = (p0 + i) < end;
        pt[i] = ok[i] ? g_sorted[p0 + i] : make_float4(9.f, 9.f, 9.f, 0.f);
    }

    ull cxx[2] = { pk2(pt[0].x, pt[1].x), pk2(pt[2].x, pt[3].x) };
    ull cyy[2] = { pk2(pt[0].y, pt[1].y), pk2(pt[2].y, pt[3].y) };
    ull czz[2] = { pk2(pt[0].z, pt[1].z), pk2(pt[2].z, pt[3].z) };

    ull hd[2] = {0ull, 0ull}, hr[2] = {0ull, 0ull}, hg[2] = {0ull, 0ull};
    ull hb[2] = {0ull, 0ull}, hw[2] = {ONE2, ONE2};

    for (int j = 0; j < m; j++) {
        ulonglong2 v0 = sm[4 * j + 0];
        ulonglong2 v1 = sm[4 * j + 1];
        float A, B2; up2(v1.y, A, B2);

        ull d2p[2];
#pragma unroll
        for (int p = 0; p < 2; p++) {
            ull dx = add2(cxx[p], v0.x);
            ull dy = add2(cyy[p], v0.y);
            ull dz = add2(czz[p], v1.x);
            ull d2 = mul2(dx, dx);
            d2 = fma2(dy, dy, d2);
            d2p[p] = fma2(dz, dz, d2);
        }
        float qa, qb, qc, qd;
        up2(d2p[0], qa, qb);
        up2(d2p[1], qc, qd);
        bool act = (qa < B2) | (qb < B2) | (qc < B2) | (qd < B2);
        if (__ballot_sync(0xffffffffu, act)) {
            ulonglong2 v2 = sm[4 * j + 2];
            ulonglong2 v3 = sm[4 * j + 3];
            float t0 = __saturatef(fmaf(sqapx(qa), -5.0f, A));
            float t1 = __saturatef(fmaf(sqapx(qb), -5.0f, A));
            float t2_ = __saturatef(fmaf(sqapx(qc), -5.0f, A));
            float t3 = __saturatef(fmaf(sqapx(qd), -5.0f, A));
            ull tp[2] = { pk2(t0, t1), pk2(t2_, t3) };
#pragma unroll
            for (int p = 0; p < 2; p++) {
                ull t2 = tp[p];
                ull omt = fma2(t2, NEG12, ONE2);
                hd[p] = fma2(t2, v2.x, mul2(omt, hd[p]));
                hr[p] = fma2(t2, v2.y, mul2(omt, hr[p]));
                hg[p] = fma2(t2, v3.x, mul2(omt, hg[p]));
                hb[p] = fma2(t2, v3.y, mul2(omt, hb[p]));
                hw[p] = mul2(omt, hw[p]);
            }
        }
    }

#pragma unroll
    for (int p = 0; p < 2; p++) {
        float d0, d1, w0, w1, r0, r1, g0, g1, b0, b1;
        up2(hd[p], d0, d1);
        up2(hw[p], w0, w1);
        up2(hr[p], r0, r1);
        up2(hg[p], g0, g1);
        up2(hb[p], b0, b1);
        float dv[2] = { d0, d1 }, wv[2] = { w0, w1 };
        float rv[2] = { r0, r1 }, gv[2] = { g0, g1 }, bv[2] = { b0, b1 };
#pragma unroll
        for (int q = 0; q < 2; q++) {
            int i = 2 * p + q;
            if (ok[i]) {
                int oi = __float_as_int(pt[i].w);
                float inv = 1.0f / (1.0f + 1e-6f - wv[q]);
                out[oi] = dv[q];
                out[NPTS + 3 * oi + 0] = __saturatef(rv[q] * inv);
                out[NPTS + 3 * oi + 1] = __saturatef(gv[q] * inv);
                out[NPTS + 3 * oi + 2] = __saturatef(bv[q] * inv);
            }
        }
    }
}

extern "C" void kernel_launch(void* const* d_in, const int* in_sizes, int n_in,
                              void* d_out, int out_size)
{
    const float* coords = (const float*)d_in[0];
    const float* shape  = (const float*)d_in[1];
    const float* color  = (const float*)d_in[2];
    const float* alpha  = (const float*)d_in[3];
    float* out = (float*)d_out;

    k_prep<<<NC / 256, 256>>>(shape, color, alpha);          // launch 0
    k_hist<<<NPTS / (4 * 256), 256>>>(coords, out);          // launch 1
    k_scan<<<1, 1024>>>();                                   // launch 2
    k_scatter<<<NPTS / (4 * 256), 256>>>(coords);            // launch 3
    k_cull<<<NC / 256, 256>>>();                             // launch 4
    k_main<<<MAXT, 128>>>(out);                              // launch 5 (ncu -s 5 lands here)
}